// round 4
// baseline (speedup 1.0000x reference)
#include <cuda_runtime.h>
#include <math.h>

namespace {
constexpr int B_  = 128;
constexpr int T_  = 288;
constexpr int FC_ = 16;
constexpr int FO_ = 64;
constexpr int U_  = 256;
constexpr int H_  = 4;
constexpr int HD_ = 64;
constexpr int BT_ = B_ * T_;          // 36864
constexpr float EPS_ = 1e-6f;
}

// ---------------- device scratch (static, no runtime alloc) ----------------
__device__ float g_x [BT_ * U_];          // running activation x [B,T,U]
__device__ float g_xg[BT_ * 3 * U_];      // GRU input gates; later aliased as q/k/v
__device__ float g_g [BT_ * U_];          // GRU outputs ys; later o-proj output
__device__ float g_a [BT_ * U_];          // attention context (pre o-proj)
__device__ float g_s [(long long)B_ * H_ * T_ * T_];  // attention scores/probs
__device__ float g_c [B_ * (U_ + FO_)];
__device__ float g_h1[B_ * 128];
__device__ float g_h2[B_ * 64];

// ---------------- helpers ----------------
template<int NW, bool DOMAX>
__device__ __forceinline__ float blk_red(float v, float* sh) {
#pragma unroll
    for (int o = 16; o > 0; o >>= 1) {
        float t = __shfl_down_sync(0xffffffffu, v, o);
        v = DOMAX ? fmaxf(v, t) : v + t;
    }
    if ((threadIdx.x & 31) == 0) sh[threadIdx.x >> 5] = v;
    __syncthreads();
    if (threadIdx.x == 0) {
        float t = sh[0];
#pragma unroll
        for (int w = 1; w < NW; w++) t = DOMAX ? fmaxf(t, sh[w]) : t + sh[w];
        sh[0] = t;
    }
    __syncthreads();
    float r = sh[0];
    __syncthreads();   // protect shared reuse by next reduction
    return r;
}

__device__ __forceinline__ float sigmoidf_(float x) {
    return 1.0f / (1.0f + expf(-x));
}

// ---------------- generic tiled SGEMM ----------------
// C[M,N] = alpha * A[M,K] @ op(B) (+ bias[n]).  op(B)=B[K,N] (TB=false) or
// op(B)=Bmat[N,K]^T (TB=true).  Batched via blockIdx.z with z = 4*b + h.
template<bool TB, bool BIAS>
__global__ void __launch_bounds__(256) gemm_kernel(
    const float* __restrict__ A, const float* __restrict__ Bm,
    const float* __restrict__ bias, float* __restrict__ C,
    int M, int N, int K, int lda, int ldb, int ldc,
    long long sAb, long long sAh, long long sBb, long long sBh,
    long long sCb, long long sCh, float alpha)
{
    __shared__ float As[64][17];
    __shared__ float Bs[16][68];

    int z = blockIdx.z, zb = z >> 2, zh = z & 3;
    A  += (long long)zb * sAb + (long long)zh * sAh;
    Bm += (long long)zb * sBb + (long long)zh * sBh;
    C  += (long long)zb * sCb + (long long)zh * sCh;

    int tid = threadIdx.x;
    int tx = tid & 15, ty = tid >> 4;
    int m0 = blockIdx.y * 64, n0 = blockIdx.x * 64;

    float acc[4][4];
#pragma unroll
    for (int i = 0; i < 4; i++)
#pragma unroll
        for (int j = 0; j < 4; j++) acc[i][j] = 0.f;

    for (int k0 = 0; k0 < K; k0 += 16) {
        {   // load A tile 64x16 -> As[row][kk]
            int kk = tid & 15, r0 = tid >> 4;
#pragma unroll
            for (int p = 0; p < 4; p++) {
                int row = r0 + p * 16;
                float v = 0.f;
                if (m0 + row < M) v = A[(long long)(m0 + row) * lda + (k0 + kk)];
                As[row][kk] = v;
            }
        }
        if (!TB) {   // B[K,N]
            int n = tid & 63, kq = tid >> 6;
#pragma unroll
            for (int p = 0; p < 4; p++) {
                int kk = kq + p * 4;
                float v = 0.f;
                if (n0 + n < N) v = Bm[(long long)(k0 + kk) * ldb + (n0 + n)];
                Bs[kk][n] = v;
            }
        } else {     // Bmat[N,K], take transpose
            int kk = tid & 15, nq = tid >> 4;
#pragma unroll
            for (int p = 0; p < 4; p++) {
                int n = nq + p * 16;
                float v = 0.f;
                if (n0 + n < N) v = Bm[(long long)(n0 + n) * ldb + (k0 + kk)];
                Bs[kk][n] = v;
            }
        }
        __syncthreads();

#pragma unroll
        for (int kk = 0; kk < 16; kk++) {
            float4 b4 = *(const float4*)(&Bs[kk][tx * 4]);
            float a0 = As[ty * 4 + 0][kk];
            float a1 = As[ty * 4 + 1][kk];
            float a2 = As[ty * 4 + 2][kk];
            float a3 = As[ty * 4 + 3][kk];
            acc[0][0] += a0 * b4.x; acc[0][1] += a0 * b4.y; acc[0][2] += a0 * b4.z; acc[0][3] += a0 * b4.w;
            acc[1][0] += a1 * b4.x; acc[1][1] += a1 * b4.y; acc[1][2] += a1 * b4.z; acc[1][3] += a1 * b4.w;
            acc[2][0] += a2 * b4.x; acc[2][1] += a2 * b4.y; acc[2][2] += a2 * b4.z; acc[2][3] += a2 * b4.w;
            acc[3][0] += a3 * b4.x; acc[3][1] += a3 * b4.y; acc[3][2] += a3 * b4.z; acc[3][3] += a3 * b4.w;
        }
        __syncthreads();
    }

#pragma unroll
    for (int i = 0; i < 4; i++) {
        int m = m0 + ty * 4 + i;
        if (m >= M) continue;
#pragma unroll
        for (int j = 0; j < 4; j++) {
            int n = n0 + tx * 4 + j;
            if (n >= N) continue;
            float v = acc[i][j] * alpha;
            if (BIAS) v += bias[n];
            C[(long long)m * ldc + n] = v;
        }
    }
}

// ---------------- layer norm (+residual variants), U=256 rows ----------------
// mode 0: out = LN(a) + res ; mode 1: out = LN(a + res) ; mode 2: out = LN(a)
__global__ void ln_kernel(const float* __restrict__ a, const float* __restrict__ res,
                          const float* __restrict__ s, const float* __restrict__ bb,
                          float* __restrict__ out, int mode)
{
    __shared__ float sh[8];
    int row = blockIdx.x;
    int u = threadIdx.x;
    long long idx = (long long)row * U_ + u;
    float r = (mode == 2) ? 0.f : res[idx];
    float v = a[idx];
    float x = (mode == 1) ? v + r : v;
    float m = blk_red<8, false>(x, sh) * (1.f / U_);
    float d = x - m;
    float var = blk_red<8, false>(d * d, sh) * (1.f / U_);
    float y = d * rsqrtf(var + EPS_) * s[u] + bb[u];
    if (mode == 0) y += r;
    out[idx] = y;
}

// ---------------- GRU single time step ----------------
// grid (16,8): 8 batch rows x 32 u per CTA; each thread does all 3 gates for (b,u).
__global__ void __launch_bounds__(256) gru_step_kernel(
    const float* __restrict__ Wh, const float* __restrict__ bhn, int t)
{
    __shared__ float hsh[8][256];
    int tid = threadIdx.x;
    int bl = tid >> 5, ul = tid & 31;
    int b0 = blockIdx.x * 8;
    int u = blockIdx.y * 32 + ul;

    if (t > 0) {
        const float* hprev = g_g + ((long long)b0 * T_ + (t - 1)) * U_;
        for (int i = tid; i < 8 * 256; i += 256)
            hsh[i >> 8][i & 255] = hprev[(long long)(i >> 8) * T_ * U_ + (i & 255)];
    } else {
        for (int i = tid; i < 8 * 256; i += 256)
            hsh[i >> 8][i & 255] = 0.f;
    }
    __syncthreads();

    float aR = 0.f, aZ = 0.f, aN = 0.f;
    if (t > 0) {
        const float* w = Wh + u;
#pragma unroll 8
        for (int k = 0; k < 256; k++) {
            float hk = hsh[bl][k];
            aR += hk * w[k * 768];
            aZ += hk * w[k * 768 + 256];
            aN += hk * w[k * 768 + 512];
        }
    }
    int b = b0 + bl;
    long long xbase = ((long long)b * T_ + t) * 768;
    float r  = sigmoidf_(g_xg[xbase + u] + aR);
    float zz = sigmoidf_(g_xg[xbase + 256 + u] + aZ);
    float n  = tanhf(g_xg[xbase + 512 + u] + r * (aN + bhn[u]));
    float hp = hsh[bl][u];
    g_g[((long long)b * T_ + t) * U_ + u] = (1.f - zz) * n + zz * hp;
}

// ---------------- softmax over rows of length T=288 ----------------
__global__ void softmax_kernel(float* __restrict__ sAll)
{
    __shared__ float sh[9];
    long long row = blockIdx.x;
    int k = threadIdx.x;
    float v = sAll[row * T_ + k];
    float mx = blk_red<9, true>(v, sh);
    float e = expf(v - mx);
    float sum = blk_red<9, false>(e, sh);
    sAll[row * T_ + k] = e / sum;
}

// ---------------- head ----------------
__global__ void pool_kernel(const float* __restrict__ other)
{
    int b = blockIdx.x, u = threadIdx.x;
    float acc = 0.f;
    const float* xp = g_x + (long long)b * T_ * U_ + u;
    for (int t = 0; t < T_; t++) acc += xp[(long long)t * U_];
    g_c[b * (U_ + FO_) + u] = acc * (1.f / T_);
    if (u < FO_) g_c[b * (U_ + FO_) + U_ + u] = other[b * FO_ + u];
}

__global__ void mlp1_kernel(const float* __restrict__ W, const float* __restrict__ bias,
                            const float* __restrict__ s, const float* __restrict__ bb)
{
    __shared__ float c[320];
    __shared__ float sh[4];
    int b = blockIdx.x, j = threadIdx.x;
    for (int i = j; i < 320; i += 128) c[i] = g_c[b * 320 + i];
    __syncthreads();
    float acc = bias[j];
#pragma unroll 8
    for (int k = 0; k < 320; k++) acc += c[k] * W[k * 128 + j];
    acc = fmaxf(acc, 0.f);
    float m = blk_red<4, false>(acc, sh) * (1.f / 128.f);
    float d = acc - m;
    float var = blk_red<4, false>(d * d, sh) * (1.f / 128.f);
    g_h1[b * 128 + j] = d * rsqrtf(var + EPS_) * s[j] + bb[j];
}

__global__ void mlp2_kernel(const float* __restrict__ W, const float* __restrict__ bias,
                            const float* __restrict__ s, const float* __restrict__ bb)
{
    __shared__ float hbuf[128];
    __shared__ float sh[2];
    int b = blockIdx.x, j = threadIdx.x;
    for (int i = j; i < 128; i += 64) hbuf[i] = g_h1[b * 128 + i];
    __syncthreads();
    float acc = bias[j];
#pragma unroll 8
    for (int k = 0; k < 128; k++) acc += hbuf[k] * W[k * 64 + j];
    acc = fmaxf(acc, 0.f);
    float m = blk_red<2, false>(acc, sh) * (1.f / 64.f);
    float d = acc - m;
    float var = blk_red<2, false>(d * d, sh) * (1.f / 64.f);
    g_h2[b * 64 + j] = d * rsqrtf(var + EPS_) * s[j] + bb[j];
}

__global__ void out_kernel(const float* __restrict__ W, const float* __restrict__ ob,
                           float* __restrict__ o)
{
    int b = threadIdx.x;
    float acc = ob[0];
#pragma unroll 8
    for (int k = 0; k < 64; k++) acc += g_h2[b * 64 + k] * W[k];
    o[b] = acc;
}

// ---------------- launcher ----------------
extern "C" void kernel_launch(void* const* d_in, const int* in_sizes, int n_in,
                              void* d_out, int out_size)
{
    (void)in_sizes; (void)n_in; (void)out_size;
    const float* cgm   = (const float*)d_in[0];
    const float* other = (const float*)d_in[1];
    const float* d0W   = (const float*)d_in[2];
    const float* d0b   = (const float*)d_in[3];
    const float* ln0s  = (const float*)d_in[4];
    const float* ln0b  = (const float*)d_in[5];
    const float* gWi   = (const float*)d_in[6];
    const float* gbi   = (const float*)d_in[7];
    const float* gWh   = (const float*)d_in[8];
    const float* gbhn  = (const float*)d_in[9];
    const float* ln1s  = (const float*)d_in[10];
    const float* ln1b  = (const float*)d_in[11];
    const float* Wq    = (const float*)d_in[12];
    const float* bq    = (const float*)d_in[13];
    const float* Wk    = (const float*)d_in[14];
    const float* bk    = (const float*)d_in[15];
    const float* Wv    = (const float*)d_in[16];
    const float* bv    = (const float*)d_in[17];
    const float* Wo    = (const float*)d_in[18];
    const float* bo    = (const float*)d_in[19];
    const float* ln2s  = (const float*)d_in[20];
    const float* ln2b  = (const float*)d_in[21];
    const float* m1W   = (const float*)d_in[22];
    const float* m1b   = (const float*)d_in[23];
    const float* lm1s  = (const float*)d_in[24];
    const float* lm1b  = (const float*)d_in[25];
    const float* m2W   = (const float*)d_in[26];
    const float* m2b   = (const float*)d_in[27];
    const float* lm2s  = (const float*)d_in[28];
    const float* lm2b  = (const float*)d_in[29];
    const float* outW  = (const float*)d_in[30];
    const float* outb  = (const float*)d_in[31];

    float *px, *pxg, *pg, *pa, *ps;
    cudaGetSymbolAddress((void**)&px,  g_x);
    cudaGetSymbolAddress((void**)&pxg, g_xg);
    cudaGetSymbolAddress((void**)&pg,  g_g);
    cudaGetSymbolAddress((void**)&pa,  g_a);
    cudaGetSymbolAddress((void**)&ps,  g_s);
    // q/k/v alias the xg buffer (xg is dead once the GRU scan finishes)
    float* pq = pxg;
    float* pk = pxg + (long long)BT_ * U_;
    float* pv = pxg + 2LL * BT_ * U_;

    // x = LN(cgm @ d0_W + d0_b)
    gemm_kernel<false, true><<<dim3(4, 576, 1), 256>>>(
        cgm, d0W, d0b, px, BT_, U_, FC_, FC_, U_, U_,
        0, 0, 0, 0, 0, 0, 1.f);
    ln_kernel<<<BT_, 256>>>(px, px, ln0s, ln0b, px, 2);

    for (int i = 0; i < 2; i++) {
        const float* Wi  = gWi  + (long long)i * U_ * 3 * U_;
        const float* bi  = gbi  + i * 3 * U_;
        const float* Wh  = gWh  + (long long)i * U_ * 3 * U_;
        const float* bhn = gbhn + i * U_;

        // input gates: xg = x @ Wi + bi   [BT,768]
        gemm_kernel<false, true><<<dim3(12, 576, 1), 256>>>(
            px, Wi, bi, pxg, BT_, 3 * U_, U_, U_, 3 * U_, 3 * U_,
            0, 0, 0, 0, 0, 0, 1.f);

        // sequential GRU scan, one grid per time step
        for (int t = 0; t < T_; t++)
            gru_step_kernel<<<dim3(16, 8), 256>>>(Wh, bhn, t);

        // x = LN(g) + x
        ln_kernel<<<BT_, 256>>>(pg, px, ln1s + i * U_, ln1b + i * U_, px, 0);

        // q,k,v projections
        gemm_kernel<false, true><<<dim3(4, 576, 1), 256>>>(
            px, Wq + (long long)i * U_ * U_, bq + i * U_, pq,
            BT_, U_, U_, U_, U_, U_, 0, 0, 0, 0, 0, 0, 1.f);
        gemm_kernel<false, true><<<dim3(4, 576, 1), 256>>>(
            px, Wk + (long long)i * U_ * U_, bk + i * U_, pk,
            BT_, U_, U_, U_, U_, U_, 0, 0, 0, 0, 0, 0, 1.f);
        gemm_kernel<false, true><<<dim3(4, 576, 1), 256>>>(
            px, Wv + (long long)i * U_ * U_, bv + i * U_, pv,
            BT_, U_, U_, U_, U_, U_, 0, 0, 0, 0, 0, 0, 1.f);

        // scores = (Q @ K^T) / 8 per (b,h)
        gemm_kernel<true, false><<<dim3(5, 5, B_ * H_), 256>>>(
            pq, pk, nullptr, ps, T_, T_, HD_, U_, U_, T_,
            (long long)T_ * U_, HD_, (long long)T_ * U_, HD_,
            (long long)H_ * T_ * T_, (long long)T_ * T_, 0.125f);

        softmax_kernel<<<B_ * H_ * T_, T_>>>(ps);

        // context = P @ V per (b,h), written into [B,T,U] head slots
        gemm_kernel<false, false><<<dim3(1, 5, B_ * H_), 256>>>(
            ps, pv, nullptr, pa, T_, HD_, T_, T_, U_, U_,
            (long long)H_ * T_ * T_, (long long)T_ * T_,
            (long long)T_ * U_, HD_, (long long)T_ * U_, HD_, 1.f);

        // o-proj into g_g (free after LN above)
        gemm_kernel<false, true><<<dim3(4, 576, 1), 256>>>(
            pa, Wo + (long long)i * U_ * U_, bo + i * U_, pg,
            BT_, U_, U_, U_, U_, U_, 0, 0, 0, 0, 0, 0, 1.f);

        // x = LN(o + x)
        ln_kernel<<<BT_, 256>>>(pg, px, ln2s + i * U_, ln2b + i * U_, px, 1);
    }

    // head
    pool_kernel<<<B_, 256>>>(other);
    mlp1_kernel<<<B_, 128>>>(m1W, m1b, lm1s, lm1b);
    mlp2_kernel<<<B_, 64>>>(m2W, m2b, lm2s, lm2b);
    out_kernel<<<1, B_>>>(outW, outb, (float*)d_out);
}